// round 17
// baseline (speedup 1.0000x reference)
#include <cuda_runtime.h>
#include <cuda_fp16.h>

// out[b,o] = min_i max(x[b,i], w[i,o])   (forward of STE expr == hard min-max)
//
// R16 analysis: neither L1 (30%) nor issue (33%) saturated -> dependent-round
// latency still dominates the scan. R14's pipeline test was confounded by
// 32 register MOVs/round. R17: PING-PONG pipeline with ZERO copies -- batches
// A/B alternate roles structurally. Next batch's LDGs are in flight across
// every ballot. Accumulating prefetched candidates past the exit bound is
// safe: the scanned set is a superset of the needed prefix and min over a
// superset (of elements all >= bound) equals the true min.
//
// Scan order: increasing x via 256-bin bucket sort; scatter stores pre-scaled
// byte offsets (idx<<11). Warp (128 o) exits when bin_floor(next x) >= max of
// its lanes' bests. Exact, order-independent.
// fp16 RN rounding bounds rel err by ~2^-11 < 1e-3.

#define DB 512
#define DI 512
#define DO 1024
#define NBIN 256

__device__ __half g_wh[DI * DO];   // fp16 w, 1 MB

// ---------- Kernel 1: w fp32 -> fp16, chip-wide MLP, ~0.5us ----------
__global__ __launch_bounds__(256) void k_convert(const float* __restrict__ w) {
    int t = blockIdx.x * 256 + threadIdx.x;          // 512 blocks, 1 float4 each
    float4 v = reinterpret_cast<const float4*>(w)[t];
    __half2 h0 = __floats2half2_rn(v.x, v.y);
    __half2 h1 = __floats2half2_rn(v.z, v.w);
    reinterpret_cast<uint2*>(g_wh)[t] =
        make_uint2(*reinterpret_cast<unsigned*>(&h0),
                   *reinterpret_cast<unsigned*>(&h1));
}

#define LOAD8(X, W, base)                                            \
    _Pragma("unroll")                                                \
    for (int kk = 0; kk < 8; kk++) {                                 \
        uint2 e = sx[(base) + kk];                                   \
        X[kk] = *reinterpret_cast<__half2*>(&e.x);                   \
        W[kk] = *reinterpret_cast<const uint2*>(wb + e.y);           \
    }

#define ACC8(X, W)                                                   \
    _Pragma("unroll")                                                \
    for (int kk = 0; kk < 8; kk++) {                                 \
        best0 = __hmin2(best0, __hmax2(X[kk],                        \
                    *reinterpret_cast<__half2*>(&W[kk].x)));         \
        best1 = __hmin2(best1, __hmax2(X[kk],                        \
                    *reinterpret_cast<__half2*>(&W[kk].y)));         \
    }

// warp-uniform exit test for all candidates at positions >= pos
#define EXITQ(pos, result)                                            \
    {                                                                 \
        unsigned nx_ = sx[pos].x & 0xFFFFu;                           \
        float nv_ = __half2float(__ushort_as_half((unsigned short)nx_)); \
        int nbin_ = min(NBIN - 1, (int)(nv_ * (float)NBIN));          \
        float bound_ = (float)nbin_ * (1.0f / (float)NBIN);           \
        __half2 m2_ = __hmax2(best0, best1);                          \
        float m_ = fmaxf(__low2float(m2_), __high2float(m2_));        \
        result = __all_sync(0xffffffffu, bound_ >= m_);               \
    }

// ---------- Kernel 2: fused sort + ping-pong pipelined pruned scan ----------
__global__ __launch_bounds__(256) void k_fused(const float* __restrict__ x,
                                               float* __restrict__ out) {
    __shared__ uint2 sx[DI];      // bin-ordered {dup-half2(x), byte-offset}, 4 KB
    __shared__ int hist[NBIN];
    __shared__ int offs[NBIN];
    __shared__ int wsum[8];

    const int b = blockIdx.x;
    const int tid = threadIdx.x;
    const int lane = tid & 31, wid = tid >> 5;

    // ---- phase 1: counting sort of x[b,:] by half-rounded value ----
    hist[tid] = 0;
    __syncthreads();

    __half h0s = __float2half_rn(x[b * DI + tid]);
    __half h1s = __float2half_rn(x[b * DI + tid + 256]);
    int bin0 = min(NBIN - 1, (int)(__half2float(h0s) * (float)NBIN));
    int bin1 = min(NBIN - 1, (int)(__half2float(h1s) * (float)NBIN));
    atomicAdd(&hist[bin0], 1);
    atomicAdd(&hist[bin1], 1);
    __syncthreads();

    // exclusive prefix over 256 bins (thread t owns bin t)
    int pv = hist[tid];
#pragma unroll
    for (int off = 1; off < 32; off <<= 1) {
        int n = __shfl_up_sync(0xffffffffu, pv, off);
        if (lane >= off) pv += n;
    }
    if (lane == 31) wsum[wid] = pv;
    __syncthreads();
    if (tid < 8) {
        int s = wsum[tid];
#pragma unroll
        for (int off = 1; off < 8; off <<= 1) {
            int n = __shfl_up_sync(0xffu, s, off);
            if (tid >= off) s += n;
        }
        wsum[tid] = s;
    }
    __syncthreads();
    offs[tid] = pv + (wid ? wsum[wid - 1] : 0) - hist[tid];
    __syncthreads();

    {
        unsigned u0 = (unsigned)__half_as_ushort(h0s);
        unsigned u1 = (unsigned)__half_as_ushort(h1s);
        int p0 = atomicAdd(&offs[bin0], 1);
        sx[p0] = make_uint2(u0 | (u0 << 16), (unsigned)tid << 11);       // byte off = idx*2048
        int p1 = atomicAdd(&offs[bin1], 1);
        sx[p1] = make_uint2(u1 | (u1 << 16), (unsigned)(tid + 256) << 11);
    }
    __syncthreads();

    // ---- phase 2: ping-pong pruned scan; warp wid owns o = wid*128 .. +127 ----
    const unsigned infu = 0x7C007C00u;   // {+inf,+inf} fp16
    __half2 best0 = *reinterpret_cast<const __half2*>(&infu);
    __half2 best1 = best0;

    const char* wb = reinterpret_cast<const char*>(g_wh + wid * 128 + lane * 4);

    __half2 ax[8]; uint2 aw[8];          // batch A
    __half2 bx2[8]; uint2 bw[8];         // batch B

    LOAD8(ax, aw, 0);
    LOAD8(bx2, bw, 8);

#pragma unroll 1
    for (int k = 0; k < DI; k += 16) {
        // --- half 1: accumulate A [k, k+8); prefetch A <- [k+16, k+24) ---
        ACC8(ax, aw);
        if (k + 16 < DI) { LOAD8(ax, aw, k + 16); }
        if (k >= 24) {                        // no warp exits before ~32
            int done; EXITQ(k + 8, done);     // covers positions >= k+8
            if (done) break;
        }
        // --- half 2: accumulate B [k+8, k+16); prefetch B <- [k+24, k+32) ---
        ACC8(bx2, bw);
        if (k + 24 < DI) { LOAD8(bx2, bw, k + 24); }
        if (k + 16 >= DI) break;
        if (k >= 16) {
            int done; EXITQ(k + 16, done);    // covers positions >= k+16
            if (done) break;
        }
    }

    float4 r;
    r.x = __low2float(best0);  r.y = __high2float(best0);
    r.z = __low2float(best1);  r.w = __high2float(best1);
    *reinterpret_cast<float4*>(&out[b * DO + wid * 128 + lane * 4]) = r;
}

extern "C" void kernel_launch(void* const* d_in, const int* in_sizes, int n_in,
                              void* d_out, int out_size) {
    const float* x = (const float*)d_in[0];   // [512, 512]
    const float* w = (const float*)d_in[1];   // [512, 1024]
    float* out = (float*)d_out;               // [512, 1024]

    k_convert<<<512, 256>>>(w);               // w -> fp16, ~0.5 us
    k_fused<<<DB, 256>>>(x, out);             // one block per row
}